// round 16
// baseline (speedup 1.0000x reference)
#include <cuda_runtime.h>
#include <math.h>

// Problem constants (fixed shapes)
#define BB   16
#define CC   64
#define HH   256
#define WW   256
#define HWSZ (HH * WW)          // 65536
#define HW4  (HWSZ / 4)         // 16384 float4 per plane

// Persistent-kernel geometry: 256 blocks x 512 threads, occ 2/SM (regs<=64)
// -> 296-CTA residency capacity on 148 SMs, all 256 blocks resident: the
// software grid barrier below is deadlock-free.
#define NBLK 256
#define NTHR 512
#define TOTT (NBLK * NTHR)      // 131072 threads

// Scratch (alloc-free rule: __device__ globals; zero-initialized)
__device__ float    g_mean   [BB * HWSZ];
__device__ float    g_max    [BB * HWSZ];
__device__ float    g_wx     [BB * HWSZ];
__device__ float    g_fused  [BB * HWSZ];
__device__ float    g_partial[BB * 128];   // 128 conv tiles per batch
__device__ float    g_cw     [BB * CC];
__device__ unsigned g_bar;                 // monotonic barrier ticket counter

__device__ __forceinline__ float sigmoidf_(float v) {
    return 1.0f / (1.0f + expf(-v));
}

// Monotonic-ticket grid barrier. Works across graph replays (counter only
// ever increases; target derived from own ticket). All blocks resident by
// construction, so spinning is safe.
__device__ __forceinline__ void grid_barrier() {
    __syncthreads();
    if (threadIdx.x == 0) {
        __threadfence();                       // publish this block's writes
        unsigned ticket = atomicAdd(&g_bar, 1u);
        unsigned target = (ticket / NBLK + 1u) * NBLK;
        while (*(volatile unsigned*)&g_bar < target) {
            __nanosleep(32);
        }
        __threadfence();                       // order spin-load before reads
    }
    __syncthreads();
}

__global__ __launch_bounds__(NTHR, 2)
void msa_fused(const float* __restrict__ x,
               const float* __restrict__ w3, const float* __restrict__ b3,
               const float* __restrict__ w5, const float* __restrict__ b5,
               const float* __restrict__ wf, const float* __restrict__ bf,
               const float* __restrict__ wr, const float* __restrict__ br,
               const float* __restrict__ wc1, const float* __restrict__ bc1,
               const float* __restrict__ wc2, const float* __restrict__ bc2,
               float* __restrict__ out) {
    __shared__ float swr[CC];
    __shared__ float sm[2][20][36];   // conv tile: (16+4) rows x (32+4) cols
    __shared__ float sw3[18];
    __shared__ float sw5[50];
    __shared__ float sc[5];           // b3, b5, wf0, wf1, bf
    __shared__ float red[NTHR];

    const int tid = threadIdx.x;
    const int tg  = blockIdx.x * NTHR + tid;

    if (tid < CC)        swr[tid] = wr[tid];
    if (tid >= 64 && tid < 82)        sw3[tid - 64] = w3[tid - 64];
    else if (tid >= 82 && tid < 132)  sw5[tid - 82] = w5[tid - 82];
    else if (tid == 132) sc[0] = b3[0];
    else if (tid == 133) sc[1] = b5[0];
    else if (tid == 134) sc[2] = wf[0];
    else if (tid == 135) sc[3] = wf[1];
    else if (tid == 136) sc[4] = bf[0];
    __syncthreads();

    // ---------------------------------------------------------------------
    // Phase 1: per-pixel channel mean / max / wr-weighted sum.
    // 262144 float4 pixel-groups over 131072 threads -> exactly 2 iterations.
    // Forward order: the TAIL of x is freshest in L2 when phase 4 starts.
    // ---------------------------------------------------------------------
#pragma unroll
    for (int it = 0; it < 2; it++) {
        const int t = it * TOTT + tg;
        const int b = t >> 14;
        const int p = t & (HW4 - 1);
        const float4* xp = reinterpret_cast<const float4*>(x)
                         + (long)b * CC * HW4 + p;

        float4 v = xp[0];
        float4 s = v;
        float4 m = v;
        float  w0 = swr[0];
        float4 wx = make_float4(w0 * v.x, w0 * v.y, w0 * v.z, w0 * v.w);

#pragma unroll 4
        for (int c = 1; c < CC; c++) {
            v = xp[(long)c * HW4];
            s.x += v.x; s.y += v.y; s.z += v.z; s.w += v.w;
            m.x = fmaxf(m.x, v.x); m.y = fmaxf(m.y, v.y);
            m.z = fmaxf(m.z, v.z); m.w = fmaxf(m.w, v.w);
            float wc = swr[c];
            wx.x = fmaf(wc, v.x, wx.x); wx.y = fmaf(wc, v.y, wx.y);
            wx.z = fmaf(wc, v.z, wx.z); wx.w = fmaf(wc, v.w, wx.w);
        }

        const float inv = 1.0f / (float)CC;
        float4 mean = make_float4(s.x * inv, s.y * inv, s.z * inv, s.w * inv);
        int o = b * HW4 + p;
        reinterpret_cast<float4*>(g_mean)[o] = mean;
        reinterpret_cast<float4*>(g_max )[o] = m;
        reinterpret_cast<float4*>(g_wx  )[o] = wx;
    }

    grid_barrier();

    // ---------------------------------------------------------------------
    // Phase 2: 3x3 + 5x5 conv (2ch->1) on [mean,max], sigmoid, 1x1 fuse,
    // scale; per-tile fused*wx partial reduction. Tile = 32x16 outputs,
    // halo 2. 2048 tiles, 8 per block (grid-stride).
    // ---------------------------------------------------------------------
    const int tx = tid & 31;
    const int ty = tid >> 5;            // 0..15

    for (int tile = blockIdx.x; tile < BB * 128; tile += NBLK) {
        const int bt  = tile >> 7;              // batch
        const int rem = tile & 127;
        const int y0  = (rem >> 3) * 16;        // 16 y-tiles
        const int x0  = (rem & 7)  * 32;        // 8 x-tiles

        const float* mb = g_mean + bt * HWSZ;
        const float* xb = g_max  + bt * HWSZ;

        __syncthreads();   // protect sm[] reuse across tile iterations
        for (int i = tid; i < 20 * 36; i += NTHR) {
            int r  = i / 36;
            int cc = i - r * 36;
            int gy = y0 + r  - 2;
            int gx = x0 + cc - 2;
            bool ok = (gy >= 0) & (gy < HH) & (gx >= 0) & (gx < WW);
            int gi = gy * WW + gx;
            sm[0][r][cc] = ok ? mb[gi] : 0.0f;
            sm[1][r][cc] = ok ? xb[gi] : 0.0f;
        }
        __syncthreads();

        float c3 = 0.0f, c5 = 0.0f;
#pragma unroll
        for (int kh = 0; kh < 3; kh++)
#pragma unroll
            for (int kw = 0; kw < 3; kw++) {
                c3 = fmaf(sw3[kh * 3 + kw],     sm[0][ty + 1 + kh][tx + 1 + kw], c3);
                c3 = fmaf(sw3[9 + kh * 3 + kw], sm[1][ty + 1 + kh][tx + 1 + kw], c3);
            }
#pragma unroll
        for (int kh = 0; kh < 5; kh++)
#pragma unroll
            for (int kw = 0; kw < 5; kw++) {
                c5 = fmaf(sw5[kh * 5 + kw],      sm[0][ty + kh][tx + kw], c5);
                c5 = fmaf(sw5[25 + kh * 5 + kw], sm[1][ty + kh][tx + kw], c5);
            }

        float a3 = sigmoidf_(c3 + sc[0]);
        float a5 = sigmoidf_(c5 + sc[1]);
        float fused = sc[2] * a3 + sc[3] * a5 + sc[4];
        fused = 0.2f + 0.8f * fused;          // MIN + (MAX-MIN)*fused

        const int gi = (y0 + ty) * WW + (x0 + tx);
        g_fused[bt * HWSZ + gi] = fused;

        // deterministic per-tile reduction of fused * wx
        red[tid] = fused * g_wx[bt * HWSZ + gi];
        __syncthreads();
#pragma unroll
        for (int off = 256; off > 0; off >>= 1) {
            if (tid < off) red[tid] += red[tid + off];
            __syncthreads();
        }
        if (tid == 0)
            g_partial[tile] = red[0];
    }

    grid_barrier();

    // ---------------------------------------------------------------------
    // Phase 3: per-batch pooled scalar + 1->32->64 MLP -> cw. Blocks 0..15.
    // ---------------------------------------------------------------------
    if (blockIdx.x < BB) {
        const int b = blockIdx.x;
        __shared__ float hs[32];
        __shared__ float pooled_s;

        red[tid] = (tid < 128) ? g_partial[b * 128 + tid] : 0.0f;
        __syncthreads();
#pragma unroll
        for (int off = 64; off > 0; off >>= 1) {
            if (tid < off) red[tid] += red[tid + off];
            __syncthreads();
        }
        if (tid == 0)
            pooled_s = red[0] * (1.0f / (float)HWSZ) + br[0];
        __syncthreads();

        if (tid < 32) {
            float hv = wc1[tid] * pooled_s + bc1[tid];
            hs[tid] = hv > 0.0f ? hv : 0.0f;
        }
        __syncthreads();

        if (tid < CC) {
            float acc = bc2[tid];
#pragma unroll
            for (int j = 0; j < 32; j++)
                acc = fmaf(wc2[tid * 32 + j], hs[j], acc);
            g_cw[b * CC + tid] = sigmoidf_(acc);
        }
    }

    grid_barrier();

    // ---------------------------------------------------------------------
    // Phase 4: out = x * (fused * cw[b,c] + 0.7).
    // 16,777,216 float4 over 131072 threads = 128 iterations, structured as
    // 16 batch windows x 8 sub-iterations, traversed in REVERSE so the first
    // window hits the x tail still L2-resident from phase 1. The fused value
    // per thread is invariant within a batch window -> loaded once per 8.
    // __ldcs/__stcs keep the 536 MB streams evict-first.
    // ---------------------------------------------------------------------
    {
        const float4* x4 = reinterpret_cast<const float4*>(x);
        float4*       o4 = reinterpret_cast<float4*>(out);
        const int pix = tg & (HW4 - 1);      // plane-local float4 index
        const int ch8 = tg >> 14;            // 0..7

        for (int k = BB - 1; k >= 0; k--) {          // batch window
            const float4 f = reinterpret_cast<const float4*>(g_fused)[k * HW4 + pix];
#pragma unroll 4
            for (int j = 7; j >= 0; j--) {
                const int i   = k * 8 + j;           // 0..127
                const int idx = i * TOTT + tg;       // global float4 index
                const int bc  = i * 8 + ch8;         // = idx >> 14

                const float cw = g_cw[bc];
                float4 xv = __ldcs(x4 + idx);
                float4 o;
                o.x = xv.x * fmaf(f.x, cw, 0.7f);
                o.y = xv.y * fmaf(f.y, cw, 0.7f);
                o.z = xv.z * fmaf(f.z, cw, 0.7f);
                o.w = xv.w * fmaf(f.w, cw, 0.7f);
                __stcs(o4 + idx, o);
            }
        }
    }
}

// ---------------------------------------------------------------------------
extern "C" void kernel_launch(void* const* d_in, const int* in_sizes, int n_in,
                              void* d_out, int out_size) {
    const float* x   = (const float*)d_in[0];
    const float* w3  = (const float*)d_in[1];
    const float* b3  = (const float*)d_in[2];
    const float* w5  = (const float*)d_in[3];
    const float* b5  = (const float*)d_in[4];
    const float* wf  = (const float*)d_in[5];
    const float* bf  = (const float*)d_in[6];
    const float* wr  = (const float*)d_in[7];
    const float* br  = (const float*)d_in[8];
    const float* wc1 = (const float*)d_in[9];
    const float* bc1 = (const float*)d_in[10];
    const float* wc2 = (const float*)d_in[11];
    const float* bc2 = (const float*)d_in[12];
    float* out = (float*)d_out;

    msa_fused<<<NBLK, NTHR>>>(x, w3, b3, w5, b5, wf, bf, wr, br,
                              wc1, bc1, wc2, bc2, out);
}

// round 17
// speedup vs baseline: 1.2532x; 1.2532x over previous
#include <cuda_runtime.h>
#include <math.h>

// Problem constants (fixed shapes from setup_inputs)
#define BB   16
#define CC   64
#define HH   256
#define WW   256
#define HWSZ (HH * WW)          // 65536
#define HW4  (HWSZ / 4)         // 16384 float4 per image plane

// Scratch (alloc-free rule: __device__ globals)
__device__ float    g_mean   [BB * HWSZ];
__device__ float    g_max    [BB * HWSZ];
__device__ float    g_wx     [BB * HWSZ];
__device__ float    g_fused  [BB * HWSZ];
__device__ float    g_partial[BB * 64];    // 64 conv tiles per batch
__device__ float    g_cw     [BB * CC];
__device__ unsigned g_done   [BB];         // monotonic tile-completion counters

__device__ __forceinline__ float sigmoidf_(float v) {
    return 1.0f / (1.0f + expf(-v));
}

// ---------------------------------------------------------------------------
// Pass 1: per-pixel channel mean, channel max, and wr-weighted channel sum.
// Reads x once (268 MB, default caching: tail stays L2-resident for k5),
// writes 3 x 4.2 MB planes. Forward block order.
// ---------------------------------------------------------------------------
__global__ __launch_bounds__(256)
void k1_pool(const float* __restrict__ x, const float* __restrict__ wr) {
    __shared__ float swr[CC];
    if (threadIdx.x < CC) swr[threadIdx.x] = wr[threadIdx.x];
    __syncthreads();

    int t = blockIdx.x * 256 + threadIdx.x;      // 0 .. BB*HW4-1
    int b = t >> 14;                             // / HW4
    int p = t & (HW4 - 1);

    const float4* xp = reinterpret_cast<const float4*>(x) + (long)b * CC * HW4 + p;

    float4 v = xp[0];
    float4 s = v;
    float4 m = v;
    float  w0 = swr[0];
    float4 wx = make_float4(w0 * v.x, w0 * v.y, w0 * v.z, w0 * v.w);

#pragma unroll 8
    for (int c = 1; c < CC; c++) {
        v = xp[(long)c * HW4];
        s.x += v.x; s.y += v.y; s.z += v.z; s.w += v.w;
        m.x = fmaxf(m.x, v.x); m.y = fmaxf(m.y, v.y);
        m.z = fmaxf(m.z, v.z); m.w = fmaxf(m.w, v.w);
        float wc = swr[c];
        wx.x = fmaf(wc, v.x, wx.x); wx.y = fmaf(wc, v.y, wx.y);
        wx.z = fmaf(wc, v.z, wx.z); wx.w = fmaf(wc, v.w, wx.w);
    }

    const float inv = 1.0f / (float)CC;
    float4 mean = make_float4(s.x * inv, s.y * inv, s.z * inv, s.w * inv);

    int o = b * HW4 + p;
    reinterpret_cast<float4*>(g_mean)[o] = mean;
    reinterpret_cast<float4*>(g_max )[o] = m;
    reinterpret_cast<float4*>(g_wx  )[o] = wx;
}

// ---------------------------------------------------------------------------
// Pass 2+3: 3x3 + 5x5 conv (2ch->1), sigmoid, 1x1 fuse, scale, per-tile
// fused*wx partials, and (in the last-finishing block per batch) the pooled
// scalar + 1->32->64 MLP -> cw. Register-tiled: 32x32-output tile per block,
// each thread computes 4 vertical outputs from an 8-row register column
// strip (weight-stationary; 3x3 taps reuse the 5x5 column strips).
// ---------------------------------------------------------------------------
__global__ __launch_bounds__(256)
void k2_conv(const float* __restrict__ w3, const float* __restrict__ b3,
             const float* __restrict__ w5, const float* __restrict__ b5,
             const float* __restrict__ wf, const float* __restrict__ bf,
             const float* __restrict__ br,
             const float* __restrict__ wc1, const float* __restrict__ bc1,
             const float* __restrict__ wc2, const float* __restrict__ bc2) {
    __shared__ float sm[2][36][36];   // (32+4)^2 halo tile per channel
    __shared__ float sw3[18];
    __shared__ float sw5[50];
    __shared__ float sc[5];           // b3, b5, wf0, wf1, bf
    __shared__ float red[256];
    __shared__ float hs[32];
    __shared__ float pooled_s;
    __shared__ int   sflag;

    const int b   = blockIdx.z;
    const int x0  = blockIdx.x * 32;
    const int y0  = blockIdx.y * 32;
    const int tid = threadIdx.x;
    const int tx  = tid & 31;
    const int rb  = (tid >> 5) * 4;   // base output row in tile (0,4,...,28)

    if (tid < 18)       sw3[tid] = w3[tid];
    else if (tid < 68)  sw5[tid - 18] = w5[tid - 18];
    else if (tid == 68) sc[0] = b3[0];
    else if (tid == 69) sc[1] = b5[0];
    else if (tid == 70) sc[2] = wf[0];
    else if (tid == 71) sc[3] = wf[1];
    else if (tid == 72) sc[4] = bf[0];

    const float* mb = g_mean + b * HWSZ;
    const float* xb = g_max  + b * HWSZ;

    for (int i = tid; i < 36 * 36; i += 256) {
        int r  = i / 36;
        int cc = i - r * 36;
        int gy = y0 + r  - 2;
        int gx = x0 + cc - 2;
        bool ok = (gy >= 0) & (gy < HH) & (gx >= 0) & (gx < WW);
        int gi = gy * WW + gx;
        sm[0][r][cc] = ok ? mb[gi] : 0.0f;
        sm[1][r][cc] = ok ? xb[gi] : 0.0f;
    }
    __syncthreads();

    float c5a[4] = {0.f, 0.f, 0.f, 0.f};
    float c3a[4] = {0.f, 0.f, 0.f, 0.f};

#pragma unroll
    for (int ch = 0; ch < 2; ch++) {
#pragma unroll
        for (int kw = 0; kw < 5; kw++) {
            float col[8];
#pragma unroll
            for (int i = 0; i < 8; i++) col[i] = sm[ch][rb + i][tx + kw];

#pragma unroll
            for (int kh = 0; kh < 5; kh++) {
                float w = sw5[ch * 25 + kh * 5 + kw];
#pragma unroll
                for (int r = 0; r < 4; r++)
                    c5a[r] = fmaf(w, col[r + kh], c5a[r]);
            }
            if (kw >= 1 && kw <= 3) {
#pragma unroll
                for (int kh = 0; kh < 3; kh++) {
                    float w = sw3[ch * 9 + kh * 3 + (kw - 1)];
#pragma unroll
                    for (int r = 0; r < 4; r++)
                        c3a[r] = fmaf(w, col[r + 1 + kh], c3a[r]);
                }
            }
        }
    }

    float psum = 0.0f;
#pragma unroll
    for (int r = 0; r < 4; r++) {
        float a3 = sigmoidf_(c3a[r] + sc[0]);
        float a5 = sigmoidf_(c5a[r] + sc[1]);
        float fused = sc[2] * a3 + sc[3] * a5 + sc[4];
        fused = 0.2f + 0.8f * fused;          // MIN + (MAX-MIN)*fused
        int gi = (y0 + rb + r) * WW + (x0 + tx);
        g_fused[b * HWSZ + gi] = fused;
        psum = fmaf(fused, g_wx[b * HWSZ + gi], psum);
    }

    // deterministic per-tile reduction of fused * wx
    red[tid] = psum;
    __syncthreads();
#pragma unroll
    for (int off = 128; off > 0; off >>= 1) {
        if (tid < off) red[tid] += red[tid + off];
        __syncthreads();
    }

    const int tile = blockIdx.y * 8 + blockIdx.x;   // 0..63 within batch
    if (tid == 0) {
        g_partial[b * 64 + tile] = red[0];
        __threadfence();                            // publish partial
        unsigned old = atomicAdd(&g_done[b], 1u);   // monotonic (replay-safe)
        sflag = (((old + 1u) & 63u) == 0u) ? 1 : 0; // last tile of this batch
        __threadfence();
    }
    __syncthreads();

    if (sflag) {
        // Last block for batch b: fixed-order sum of 64 partials -> MLP -> cw.
        if (tid < 64) red[tid] = __ldcg(&g_partial[b * 64 + tid]);
        __syncthreads();
#pragma unroll
        for (int off = 32; off > 0; off >>= 1) {
            if (tid < off) red[tid] += red[tid + off];
            __syncthreads();
        }
        if (tid == 0)
            pooled_s = red[0] * (1.0f / (float)HWSZ) + br[0];
        __syncthreads();

        if (tid < 32) {
            float hv = wc1[tid] * pooled_s + bc1[tid];
            hs[tid] = hv > 0.0f ? hv : 0.0f;
        }
        __syncthreads();

        if (tid < CC) {
            float acc = bc2[tid];
#pragma unroll
            for (int j = 0; j < 32; j++)
                acc = fmaf(wc2[tid * 32 + j], hs[j], acc);
            g_cw[b * CC + tid] = sigmoidf_(acc);
        }
    }
}

// ---------------------------------------------------------------------------
// Pass 5: out = x * (fused * cw[b,c] + 0.7). REVERSED block order: consumes
// the tail of x first (freshest in L2 after k1). __ldcs/__stcs keep the big
// streams evict-first. 2 float4 per thread for ILP.
// ---------------------------------------------------------------------------
__global__ __launch_bounds__(256)
void k5_apply(const float* __restrict__ x, float* __restrict__ out) {
    const int blk  = (int)gridDim.x - 1 - blockIdx.x;   // reversed traversal
    const int base = blk * 512 + threadIdx.x;           // float4 index
    const int bc   = blk >> 5;                          // 512*32 = 16384 = HW4
    const int b    = bc >> 6;

    const float cw = g_cw[bc];
    const float4* x4 = reinterpret_cast<const float4*>(x);
    const float4* f4 = reinterpret_cast<const float4*>(g_fused) + b * HW4;
    float4*       o4 = reinterpret_cast<float4*>(out);

    const int hw0 = base & (HW4 - 1);
    const int hw1 = (base + 256) & (HW4 - 1);

    float4 xv0 = __ldcs(x4 + base);
    float4 xv1 = __ldcs(x4 + base + 256);
    float4 f0  = f4[hw0];
    float4 f1  = f4[hw1];

    float4 o0, o1;
    o0.x = xv0.x * fmaf(f0.x, cw, 0.7f);
    o0.y = xv0.y * fmaf(f0.y, cw, 0.7f);
    o0.z = xv0.z * fmaf(f0.z, cw, 0.7f);
    o0.w = xv0.w * fmaf(f0.w, cw, 0.7f);
    o1.x = xv1.x * fmaf(f1.x, cw, 0.7f);
    o1.y = xv1.y * fmaf(f1.y, cw, 0.7f);
    o1.z = xv1.z * fmaf(f1.z, cw, 0.7f);
    o1.w = xv1.w * fmaf(f1.w, cw, 0.7f);

    __stcs(o4 + base,       o0);
    __stcs(o4 + base + 256, o1);
}

// ---------------------------------------------------------------------------
extern "C" void kernel_launch(void* const* d_in, const int* in_sizes, int n_in,
                              void* d_out, int out_size) {
    const float* x   = (const float*)d_in[0];
    const float* w3  = (const float*)d_in[1];
    const float* b3  = (const float*)d_in[2];
    const float* w5  = (const float*)d_in[3];
    const float* b5  = (const float*)d_in[4];
    const float* wf  = (const float*)d_in[5];
    const float* bf  = (const float*)d_in[6];
    const float* wr  = (const float*)d_in[7];
    const float* br  = (const float*)d_in[8];
    const float* wc1 = (const float*)d_in[9];
    const float* bc1 = (const float*)d_in[10];
    const float* wc2 = (const float*)d_in[11];
    const float* bc2 = (const float*)d_in[12];
    float* out = (float*)d_out;

    // Pass 1: channel pool + weighted sum. BB*HW4/256 = 1024 blocks.
    k1_pool<<<(BB * HW4) / 256, 256>>>(x, wr);

    // Pass 2+3: convs + fuse + pool partials + (last block per batch) MLP.
    dim3 g2(8, 8, BB);   // 8 x-tiles, 8 y-tiles (32x32 outputs), 16 batches
    k2_conv<<<g2, 256>>>(w3, b3, w5, b5, wf, bf, br, wc1, bc1, wc2, bc2);

    // Pass 5: final elementwise, reversed, 2 float4/thread. 32768 blocks.
    k5_apply<<<(BB * CC * HW4) / 512, 256>>>(x, out);
}